// round 14
// baseline (speedup 1.0000x reference)
#include <cuda_runtime.h>
#include <cuda_bf16.h>
#include <cstdint>

// ---------------------------------------------------------------------------
// Net_15762529976343 — STN head. 5 GEMMs (M=200, K=18432) via mma.sync bf16
// hi/lo 3-term fp32 emulation (harness PTX targets plain sm_103 — no tcgen05).
// R14: R8 structure + rebalanced warp tiling (wn=wid&3, wm=wid>>2) so the
// dead M-padding subtiles (rows 200..255) are skipped EVENLY across SMSPs:
// per-chunk critical path drops 18.75% on every GEMM.
// ---------------------------------------------------------------------------

#define MM   200
#define KKT  18432
#define CCH  2048

// ---- scratch ----
__device__ __align__(128) float g_A[MM * KKT];
__device__ __align__(128) float g_C[MM * CCH];
__device__ __align__(128) float g_f[MM * CCH];
__device__ __align__(128) float g_xs[MM * CCH];
__device__ __align__(128) float g_h[MM * 512];
__device__ __align__(128) float g_L[MM * 201];
__device__ __align__(128) float g_part[3686400];      // 9*200*2048 fp32 max
__device__ float g_mean[CCH], g_rstd[CCH];
__device__ float g_grids[8 * 225 * 2];

// ---------------------------------------------------------------------------
// helpers
// ---------------------------------------------------------------------------
__device__ __forceinline__ uint32_t smem_u32(const void* p) {
    uint32_t a;
    asm("{ .reg .u64 t; cvta.to.shared.u64 t, %1; cvt.u32.u64 %0, t; }"
        : "=r"(a) : "l"(p));
    return a;
}
__device__ __forceinline__ uint32_t swz(uint32_t off) {
    return off ^ ((off >> 3) & 0x70);
}
// fp32 pair -> packed bf16x2 (hi) and bf16x2 (lo)
__device__ __forceinline__ void split2(float x, float y, uint32_t& hi, uint32_t& lo) {
    __nv_bfloat16 hx = __float2bfloat16(x), hy = __float2bfloat16(y);
    float lx = x - __bfloat162float(hx), ly = y - __bfloat162float(hy);
    hi = ((uint32_t)__bfloat16_as_ushort(hy) << 16) | (uint32_t)__bfloat16_as_ushort(hx);
    __nv_bfloat16 gx = __float2bfloat16(lx), gy = __float2bfloat16(ly);
    lo = ((uint32_t)__bfloat16_as_ushort(gy) << 16) | (uint32_t)__bfloat16_as_ushort(gx);
}
__device__ __forceinline__ void ldsm4(uint32_t* r, uint32_t addr) {
    asm volatile("ldmatrix.sync.aligned.m8n8.x4.shared.b16 {%0,%1,%2,%3}, [%4];"
                 : "=r"(r[0]), "=r"(r[1]), "=r"(r[2]), "=r"(r[3]) : "r"(addr));
}
__device__ __forceinline__ void mma16816(float* d, const uint32_t* a, const uint32_t* b) {
    asm volatile(
        "mma.sync.aligned.m16n8k16.row.col.f32.bf16.bf16.f32 "
        "{%0,%1,%2,%3},{%4,%5,%6,%7},{%8,%9},{%0,%1,%2,%3};"
        : "+f"(d[0]), "+f"(d[1]), "+f"(d[2]), "+f"(d[3])
        : "r"(a[0]), "r"(a[1]), "r"(a[2]), "r"(a[3]), "r"(b[0]), "r"(b[1]));
}

// SMEM planes (single buffer, 64KB): [AH 16K][AL 16K][BH 16K][BL 16K]
#define OFF_AH 0
#define OFF_AL 16384
#define OFF_BH 32768
#define OFF_BL 49152
#define SMEM_TC_BYTES 65536

// ---------------------------------------------------------------------------
// GEMM: C[m,n] = sum_k A[m,k]*Bw[n,k]  (A = g_A fp32, Bw fp32)
// CTA tile M=128 x N=128, K-slice z (split-K). 256 threads, 8 MMA warps.
// Warp tiling: wn = wid&3 (32 N-cols), wm = wid>>2 (64 M-rows, 4 mf-frags).
// SMSPs thus mix wm=0 and wm=1 warps -> dead-frag skipping is balanced.
// Pipeline (R8): convert/store(ch) -> sync -> prefetch(ch+1) -> MMA(ch) -> sync.
// Output fp32 partials -> g_part[z][m][n].
// ---------------------------------------------------------------------------
__global__ void __launch_bounds__(256, 1) sgemm_tc(const float* __restrict__ Bw,
                                                   int N, int klen) {
    extern __shared__ char smem[];
    uint32_t sb = smem_u32(smem);
    int tid = threadIdx.x, wid = tid >> 5, lid = tid & 31;
    int m0 = blockIdx.y * 128, n0 = blockIdx.x * 128, z = blockIdx.z;
    int nch = klen / 64;
    long k0 = (long)z * klen;
    int f4 = tid & 15, rb = tid >> 4;
    const float4 z4 = make_float4(0.f, 0.f, 0.f, 0.f);

    int wn = wid & 3, wm = wid >> 2;
    // frag validity: any real rows in m-frag (wm*64 + mf*16 .. +15)?
    bool mval[4];
#pragma unroll
    for (int mf = 0; mf < 4; mf++)
        mval[mf] = (m0 + wm * 64 + mf * 16) < MM;

    float acc[4][4][4];
#pragma unroll
    for (int i = 0; i < 4; i++)
#pragma unroll
        for (int j = 0; j < 4; j++)
#pragma unroll
            for (int q = 0; q < 4; q++) acc[i][j][q] = 0.f;

    const float* Arow = g_A + (long)(m0 + rb) * KKT + f4 * 4;
    const float* Brow = Bw  + (long)(n0 + rb) * KKT + f4 * 4;
    bool amask[8], bmask[8];
#pragma unroll
    for (int p = 0; p < 8; p++) {
        amask[p] = (m0 + p * 16 + rb) < MM;
        bmask[p] = (n0 + p * 16 + rb) < N;
    }

    float4 a4[8], b4[8];
    // prologue: prefetch chunk 0
#pragma unroll
    for (int p = 0; p < 8; p++) {
        a4[p] = amask[p] ? *(const float4*)(Arow + (long)p * 16 * KKT + k0) : z4;
        b4[p] = bmask[p] ? *(const float4*)(Brow + (long)p * 16 * KKT + k0) : z4;
    }

    for (int ch = 0; ch < nch; ch++) {
        // convert + store current chunk's registers into swizzled bf16 planes
#pragma unroll
        for (int p = 0; p < 8; p++) {
            int r = p * 16 + rb;
            uint32_t sw = swz((uint32_t)(r * 128 + f4 * 8));
            uint32_t h0, l0, h1, l1;
            split2(a4[p].x, a4[p].y, h0, l0); split2(a4[p].z, a4[p].w, h1, l1);
            *(uint2*)(smem + OFF_AH + sw) = make_uint2(h0, h1);
            *(uint2*)(smem + OFF_AL + sw) = make_uint2(l0, l1);
            split2(b4[p].x, b4[p].y, h0, l0); split2(b4[p].z, b4[p].w, h1, l1);
            *(uint2*)(smem + OFF_BH + sw) = make_uint2(h0, h1);
            *(uint2*)(smem + OFF_BL + sw) = make_uint2(l0, l1);
        }
        __syncthreads();

        // issue next chunk's global loads NOW; they complete under the MMAs
        if (ch + 1 < nch) {
            long kc = k0 + (long)(ch + 1) * 64;
#pragma unroll
            for (int p = 0; p < 8; p++) {
                a4[p] = amask[p] ? *(const float4*)(Arow + (long)p * 16 * KKT + kc) : z4;
                b4[p] = bmask[p] ? *(const float4*)(Brow + (long)p * 16 * KKT + kc) : z4;
            }
        }

#pragma unroll
        for (int ks = 0; ks < 4; ks++) {
            // A fragments (16x16): up to 4 m-frags, hi+lo planes (skip dead)
            uint32_t ah[4][4], al[4][4];
#pragma unroll
            for (int mf = 0; mf < 4; mf++) {
                if (mval[mf]) {
                    uint32_t row = (uint32_t)(wm * 64 + mf * 16 + (lid & 15));
                    uint32_t col = (uint32_t)(ks * 32 + (lid >> 4) * 16);
                    uint32_t o = swz(row * 128 + col);
                    ldsm4(ah[mf], sb + OFF_AH + o);
                    ldsm4(al[mf], sb + OFF_AL + o);
                }
            }
            // B fragments: 2 x4-loads cover this warp's 32 N-cols (4 n8-frags)
#pragma unroll
            for (int bq = 0; bq < 2; bq++) {
                uint32_t row = (uint32_t)(wn * 32 + bq * 16 + (lid & 7) +
                                          ((lid >> 4) & 1) * 8);
                uint32_t col = (uint32_t)(ks * 32 + ((lid >> 3) & 1) * 16);
                uint32_t o = swz(row * 128 + col);
                uint32_t bh[4], bl[4];
                ldsm4(bh, sb + OFF_BH + o);
                ldsm4(bl, sb + OFF_BL + o);
#pragma unroll
                for (int mf = 0; mf < 4; mf++) {
                    if (mval[mf]) {
#pragma unroll
                        for (int h = 0; h < 2; h++) {
                            int nf = bq * 2 + h;
                            mma16816(acc[mf][nf], ah[mf], bh + 2 * h);
                            mma16816(acc[mf][nf], ah[mf], bl + 2 * h);
                            mma16816(acc[mf][nf], al[mf], bh + 2 * h);
                        }
                    }
                }
            }
        }
        __syncthreads();
    }

    // epilogue: d-frag mapping: rows lane/4 (+8), cols (lane%4)*2 (+1)
    float* dst = g_part + (long)z * MM * N;
    int gr = lid >> 2, gc = (lid & 3) << 1;
#pragma unroll
    for (int mf = 0; mf < 4; mf++) {
#pragma unroll
        for (int nf = 0; nf < 4; nf++) {
            int mrow = m0 + wm * 64 + mf * 16 + gr;
            int ncol = n0 + wn * 32 + nf * 8 + gc;
            if (mrow < MM) {
                if (ncol < N)     dst[(long)mrow * N + ncol]     = acc[mf][nf][0];
                if (ncol + 1 < N) dst[(long)mrow * N + ncol + 1] = acc[mf][nf][1];
            }
            if (mrow + 8 < MM) {
                if (ncol < N)     dst[(long)(mrow + 8) * N + ncol]     = acc[mf][nf][2];
                if (ncol + 1 < N) dst[(long)(mrow + 8) * N + ncol + 1] = acc[mf][nf][3];
            }
        }
    }
}

// ---------------------------------------------------------------------------
// im2col from x [8,2048,10,10], k=3 s=2 p=1  -> A[m][c*9+u*3+v]
// ---------------------------------------------------------------------------
__global__ void im2col_x_k(const float* __restrict__ x) {
    int t = blockIdx.x * 256 + threadIdx.x;
    if (t >= MM * CCH) return;
    int c = t & 2047, m = t >> 11;
    int b = m / 25, pos = m % 25;
    int oy = pos / 5, ox = pos % 5;
    const float* xb = x + ((long)(b * CCH + c)) * 100;
    float* ab = g_A + (long)m * KKT + c * 9;
#pragma unroll
    for (int u = 0; u < 3; u++) {
        int iy = 2 * oy - 1 + u;
#pragma unroll
        for (int v = 0; v < 3; v++) {
            int ix = 2 * ox - 1 + v;
            float val = (iy >= 0 && iy < 10 && ix >= 0 && ix < 10) ? xb[iy * 10 + ix] : 0.f;
            ab[u * 3 + v] = val;
        }
    }
}

// im2col from a 5x5 map (layout [b][pos][c]), k=3 s=1 p=1. sel: 0->g_f, 1->g_xs
__global__ void im2col5_k(int sel) {
    int t = blockIdx.x * 256 + threadIdx.x;
    if (t >= MM * CCH) return;
    int c = t & 2047, m = t >> 11;
    int b = m / 25, pos = m % 25;
    int oy = pos / 5, ox = pos % 5;
    const float* src = sel ? g_xs : g_f;
    float* ab = g_A + (long)m * KKT + c * 9;
#pragma unroll
    for (int u = 0; u < 3; u++) {
        int iy = oy - 1 + u;
#pragma unroll
        for (int v = 0; v < 3; v++) {
            int ix = ox - 1 + v;
            float val = (iy >= 0 && iy < 5 && ix >= 0 && ix < 5)
                        ? src[(b * 25 + iy * 5 + ix) * CCH + c] : 0.f;
            ab[u * 3 + v] = val;
        }
    }
}

// split-K reduction: dst_sel 0 -> g_C, 1 -> g_h, 2 -> g_L
__global__ void reduce_k(int dst_sel, int N, int nz) {
    int i = blockIdx.x * 256 + threadIdx.x;
    int tot = MM * N;
    if (i >= tot) return;
    float s = 0.f;
    for (int zz = 0; zz < nz; zz++) s += g_part[(long)zz * tot + i];
    float* dst = (dst_sel == 0) ? g_C : ((dst_sel == 1) ? g_h : g_L);
    dst[i] = s;
}

// BN batch statistics over m (200 samples) per channel n (of g_C)
__global__ void bn_stats_k() {
    __shared__ float ss[2], ss2[2];
    int n = blockIdx.x, tid = threadIdx.x;
    float s = 0.f, s2 = 0.f;
    for (int m = tid; m < MM; m += 64) {
        float v = g_C[(long)m * CCH + n];
        s += v; s2 += v * v;
    }
#pragma unroll
    for (int o = 16; o > 0; o >>= 1) {
        s  += __shfl_xor_sync(0xffffffffu, s,  o);
        s2 += __shfl_xor_sync(0xffffffffu, s2, o);
    }
    if ((tid & 31) == 0) { ss[tid >> 5] = s; ss2[tid >> 5] = s2; }
    __syncthreads();
    if (tid == 0) {
        float S = ss[0] + ss[1], S2 = ss2[0] + ss2[1];
        float mean = S * (1.f / 200.f);
        float var  = S2 * (1.f / 200.f) - mean * mean;
        g_mean[n] = mean;
        g_rstd[n] = rsqrtf(var + 1e-5f);
    }
}

// dst_sel: 0 -> g_f, 1 -> g_xs
__global__ void bn_apply_k(const float* __restrict__ gam, const float* __restrict__ bet,
                           int dst_sel, int relu) {
    int i = blockIdx.x * 256 + threadIdx.x;
    if (i >= MM * CCH) return;
    int n = i & 2047;
    float v = (g_C[i] - g_mean[n]) * g_rstd[n] * gam[n] + bet[n];
    if (relu) v = fmaxf(v, 0.f);
    float* dst = dst_sel ? g_xs : g_f;
    dst[i] = v;
}

// fc2 (4x512) per (b,pos) on relu(g_h); theta -> output; 9 grid pts -> g_grids
__global__ void fc2_theta_k(const float* __restrict__ fc2_w, float* __restrict__ out_theta) {
    int m = blockIdx.x;
    int tid = threadIdx.x;    // 128
    __shared__ float sh[512];
    __shared__ float sp[4];
    for (int i = tid; i < 512; i += 128) sh[i] = fmaxf(g_h[m * 512 + i], 0.f);
    __syncthreads();
    int w = tid >> 5, lane = tid & 31;
    float s = 0.f;
    for (int j = lane; j < 512; j += 32) s += sh[j] * fc2_w[w * 512 + j];
#pragma unroll
    for (int o = 16; o > 0; o >>= 1) s += __shfl_xor_sync(0xffffffffu, s, o);
    if (lane == 0) sp[w] = s;
    __syncthreads();
    if (tid == 0) {
        float p0 = sp[0], p1 = sp[1], p2 = sp[2], p3 = sp[3];
        float th[6] = {1.f + p0, 0.f, p1, 0.f, 1.f + p2, p3};
#pragma unroll
        for (int t = 0; t < 6; t++) out_theta[m * 6 + t] = th[t];
        int pi = (m % 25) / 5, pj = (m % 25) % 5;
#pragma unroll
        for (int u = 0; u < 3; u++)
#pragma unroll
            for (int v = 0; v < 3; v++) {
                float lx = (float)(pj + v) * (1.f / 3.f) - 1.f;
                float ly = (float)(pi + u) * (1.f / 3.f) - 1.f;
                int pt = m * 9 + u * 3 + v;
                g_grids[pt * 2 + 0] = (1.f + p0) * lx + p1;
                g_grids[pt * 2 + 1] = (1.f + p2) * ly + p3;
            }
    }
}

// bilinear sample of f (zero-padded ring), writes im2col A[m][c*9+k]
__global__ void sample_k(void) {
    int pt = blockIdx.x;          // m*9 + k
    int m = pt / 9, k = pt % 9;
    int b = m / 25;
    float gx = (g_grids[pt * 2 + 0] + 1.f) * 3.f;
    float gy = (g_grids[pt * 2 + 1] + 1.f) * 3.f;
    float x0f = floorf(gx), y0f = floorf(gy);
    int   x0i = (int)x0f,  y0i = (int)y0f;
    float wx1 = gx - x0f, wx0 = 1.f - wx1;
    float wy1 = gy - y0f, wy0 = 1.f - wy1;
    int   cx[2] = {x0i, x0i + 1}, cy[2] = {y0i, y0i + 1};
    float wxx[2] = {wx0, wx1},    wyy[2] = {wy0, wy1};
    float wgt[4];
    int   off[4];
#pragma unroll
    for (int a = 0; a < 2; a++)
#pragma unroll
        for (int c2 = 0; c2 < 2; c2++) {
            int xi = cx[c2], yi = cy[a];
            bool val = (xi >= 1 && xi <= 5 && yi >= 1 && yi <= 5);
            wgt[a * 2 + c2] = val ? wyy[a] * wxx[c2] : 0.f;
            off[a * 2 + c2] = val ? ((b * 25 + (yi - 1) * 5 + (xi - 1)) * CCH) : 0;
        }
    float* ab = g_A + (long)m * KKT + k;
    for (int c = threadIdx.x; c < CCH; c += blockDim.x) {
        float v = wgt[0] * g_f[off[0] + c] + wgt[1] * g_f[off[1] + c]
                + wgt[2] * g_f[off[2] + c] + wgt[3] * g_f[off[3] + c];
        ab[(long)c * 9] = v;
    }
}

// joint softmax over 201*25 per batch
__global__ void softmax_k(const float* __restrict__ bias, float* __restrict__ out) {
    int b = blockIdx.x;
    int tid = threadIdx.x;            // 512
    __shared__ float sm[5025];
    __shared__ float red[512];
    float lmax = -3.0e38f;
    for (int idx = tid; idx < 5025; idx += 512) {
        int o = idx / 25, pos = idx % 25;
        float v = g_L[(b * 25 + pos) * 201 + o] + bias[o];
        sm[idx] = v;
        lmax = fmaxf(lmax, v);
    }
    red[tid] = lmax;
    __syncthreads();
    for (int s = 256; s > 0; s >>= 1) {
        if (tid < s) red[tid] = fmaxf(red[tid], red[tid + s]);
        __syncthreads();
    }
    float mx = red[0];
    __syncthreads();
    float lsum = 0.f;
    for (int idx = tid; idx < 5025; idx += 512) {
        float e = expf(sm[idx] - mx);
        sm[idx] = e;
        lsum += e;
    }
    red[tid] = lsum;
    __syncthreads();
    for (int s = 256; s > 0; s >>= 1) {
        if (tid < s) red[tid] += red[tid + s];
        __syncthreads();
    }
    float inv = 1.f / red[0];
    __syncthreads();
    float* s_out = out + 1608;
    for (int idx = tid; idx < 5025; idx += 512)
        s_out[b * 5025 + idx] = sm[idx] * inv;
    for (int o = tid; o < 201; o += 512) {
        float acc = 0.f;
        for (int pos = 0; pos < 25; pos++) acc += sm[o * 25 + pos];
        out[b * 201 + o] = acc * inv;
    }
}

// ---------------------------------------------------------------------------
extern "C" void kernel_launch(void* const* d_in, const int* in_sizes, int n_in,
                              void* d_out, int out_size) {
    const float* x           = (const float*)d_in[0];
    const float* conv_last_w = (const float*)d_in[3];
    const float* bn_last_g   = (const float*)d_in[4];
    const float* bn_last_b   = (const float*)d_in[5];
    const float* loc_w1      = (const float*)d_in[6];
    const float* loc_g1      = (const float*)d_in[7];
    const float* loc_b1      = (const float*)d_in[8];
    const float* loc_w2      = (const float*)d_in[9];
    const float* loc_g2      = (const float*)d_in[10];
    const float* loc_b2      = (const float*)d_in[11];
    const float* fc1_w       = (const float*)d_in[12];
    const float* fc2_w       = (const float*)d_in[13];
    const float* conv_stn_w  = (const float*)d_in[14];
    const float* conv_stn_b  = (const float*)d_in[15];
    float* out = (float*)d_out;
    float* out_theta = out + 1608 + 40200;

    cudaFuncSetAttribute(sgemm_tc, cudaFuncAttributeMaxDynamicSharedMemorySize,
                         SMEM_TC_BYTES);

    const int ELT_BLOCKS = (MM * CCH + 255) / 256;   // 1600

    // ---- backbone tail: conv_last + BN -> f ----
    im2col_x_k<<<ELT_BLOCKS, 256>>>(x);
    sgemm_tc<<<dim3(16, 2, 9), 256, SMEM_TC_BYTES>>>(conv_last_w, 2048, 2048);
    reduce_k<<<(MM * 2048 + 255) / 256, 256>>>(0, 2048, 9);
    bn_stats_k<<<2048, 64>>>();
    bn_apply_k<<<ELT_BLOCKS, 256>>>(bn_last_g, bn_last_b, 0, 0);

    // ---- localization conv1 ----
    im2col5_k<<<ELT_BLOCKS, 256>>>(0);
    sgemm_tc<<<dim3(16, 2, 9), 256, SMEM_TC_BYTES>>>(loc_w1, 2048, 2048);
    reduce_k<<<(MM * 2048 + 255) / 256, 256>>>(0, 2048, 9);
    bn_stats_k<<<2048, 64>>>();
    bn_apply_k<<<ELT_BLOCKS, 256>>>(loc_g1, loc_b1, 1, 1);

    // ---- localization conv2 ----
    im2col5_k<<<ELT_BLOCKS, 256>>>(1);
    sgemm_tc<<<dim3(16, 2, 9), 256, SMEM_TC_BYTES>>>(loc_w2, 2048, 2048);
    reduce_k<<<(MM * 2048 + 255) / 256, 256>>>(0, 2048, 9);
    bn_stats_k<<<2048, 64>>>();
    bn_apply_k<<<ELT_BLOCKS, 256>>>(loc_g2, loc_b2, 1, 1);

    // ---- fc1 (3x3 conv, 512 outputs) ----
    im2col5_k<<<ELT_BLOCKS, 256>>>(1);
    sgemm_tc<<<dim3(4, 2, 18), 256, SMEM_TC_BYTES>>>(fc1_w, 512, 1024);
    reduce_k<<<(MM * 512 + 255) / 256, 256>>>(1, 512, 18);

    // ---- fc2 + theta + grids ----
    fc2_theta_k<<<200, 128>>>(fc2_w, out_theta);

    // ---- bilinear sample -> im2col A ----
    sample_k<<<1800, 256>>>();

    // ---- conv_stn GEMM ----
    sgemm_tc<<<dim3(2, 2, 36), 256, SMEM_TC_BYTES>>>(conv_stn_w, 201, 512);
    reduce_k<<<(MM * 201 + 255) / 256, 256>>>(2, 201, 36);

    // ---- joint softmax + outputs ----
    softmax_k<<<8, 512>>>(conv_stn_b, out);
}

// round 15
// speedup vs baseline: 1.1601x; 1.1601x over previous
#include <cuda_runtime.h>
#include <cuda_bf16.h>
#include <cstdint>

// ---------------------------------------------------------------------------
// Net_15762529976343 — STN head. 5 GEMMs (M=200, K=18432) via mma.sync bf16
// hi/lo 3-term fp32 emulation (harness PTX targets plain sm_103 — no tcgen05).
// R15: warp-specialized GEMM. 8 consumer warps (R8 tiling, untouched) +
// 4 producer warps: A via cp.async from pre-split bf16 planes (no regs, no
// convert), B via reg-prefetch + convert issued a full barrier-period ahead.
// Double-buffered SMEM (2x64KB), ONE __syncthreads per chunk. The ~44%
// per-chunk overhead (convert/LDG/sync) now overlaps the MMA floor.
// ---------------------------------------------------------------------------

#define MM   200
#define KKT  18432
#define CCH  2048

// ---- scratch ----
__device__ __align__(128) uint16_t g_Ah[MM * KKT];     // A hi-plane (bf16)
__device__ __align__(128) uint16_t g_Al[MM * KKT];     // A lo-plane (bf16)
__device__ __align__(128) float g_C[MM * CCH];
__device__ __align__(128) float g_f[MM * CCH];
__device__ __align__(128) float g_xs[MM * CCH];
__device__ __align__(128) float g_h[MM * 512];
__device__ __align__(128) float g_L[MM * 201];
__device__ __align__(128) float g_part[3686400];      // 9*200*2048 fp32 max
__device__ float g_mean[CCH], g_rstd[CCH];
__device__ float g_grids[8 * 225 * 2];

// ---------------------------------------------------------------------------
// helpers
// ---------------------------------------------------------------------------
__device__ __forceinline__ uint32_t smem_u32(const void* p) {
    uint32_t a;
    asm("{ .reg .u64 t; cvta.to.shared.u64 t, %1; cvt.u32.u64 %0, t; }"
        : "=r"(a) : "l"(p));
    return a;
}
__device__ __forceinline__ uint32_t swz(uint32_t off) {
    return off ^ ((off >> 3) & 0x70);
}
// fp32 pair -> packed bf16x2 (hi) and bf16x2 (lo)
__device__ __forceinline__ void split2(float x, float y, uint32_t& hi, uint32_t& lo) {
    __nv_bfloat16 hx = __float2bfloat16(x), hy = __float2bfloat16(y);
    float lx = x - __bfloat162float(hx), ly = y - __bfloat162float(hy);
    hi = ((uint32_t)__bfloat16_as_ushort(hy) << 16) | (uint32_t)__bfloat16_as_ushort(hx);
    __nv_bfloat16 gx = __float2bfloat16(lx), gy = __float2bfloat16(ly);
    lo = ((uint32_t)__bfloat16_as_ushort(gy) << 16) | (uint32_t)__bfloat16_as_ushort(gx);
}
// single fp32 -> (hi,lo) bf16 bits
__device__ __forceinline__ void split1(float x, uint16_t& h, uint16_t& l) {
    __nv_bfloat16 hb = __float2bfloat16(x);
    float r = x - __bfloat162float(hb);
    h = __bfloat16_as_ushort(hb);
    l = __bfloat16_as_ushort(__float2bfloat16(r));
}
__device__ __forceinline__ void ldsm4(uint32_t* r, uint32_t addr) {
    asm volatile("ldmatrix.sync.aligned.m8n8.x4.shared.b16 {%0,%1,%2,%3}, [%4];"
                 : "=r"(r[0]), "=r"(r[1]), "=r"(r[2]), "=r"(r[3]) : "r"(addr));
}
__device__ __forceinline__ void mma16816(float* d, const uint32_t* a, const uint32_t* b) {
    asm volatile(
        "mma.sync.aligned.m16n8k16.row.col.f32.bf16.bf16.f32 "
        "{%0,%1,%2,%3},{%4,%5,%6,%7},{%8,%9},{%0,%1,%2,%3};"
        : "+f"(d[0]), "+f"(d[1]), "+f"(d[2]), "+f"(d[3])
        : "r"(a[0]), "r"(a[1]), "r"(a[2]), "r"(a[3]), "r"(b[0]), "r"(b[1]));
}
// 16B cp.async with src-size zero-fill (sz=0 -> 16 zero bytes)
__device__ __forceinline__ void cpa16(uint32_t dst, const void* src, int sz) {
    asm volatile("cp.async.cg.shared.global [%0], [%1], 16, %2;"
                 :: "r"(dst), "l"(src), "r"(sz) : "memory");
}

// SMEM: 2 buffers x 64KB: [AH 16K][AL 16K][BH 16K][BL 16K]
#define BUF_BYTES 65536
#define OFF_AH 0
#define OFF_AL 16384
#define OFF_BH 32768
#define OFF_BL 49152
#define SMEM_TC_BYTES (2 * BUF_BYTES)

// ---------------------------------------------------------------------------
// GEMM: C[m,n] = sum_k A[m,k]*Bw[n,k]  (A = g_Ah/g_Al bf16 planes, Bw fp32)
// CTA tile M=128 x N=128, K-slice z (split-K). 384 threads:
//   warps 0-7  : MMA consumers (R8 tiling: wm=wid&3 over M, wn=wid>>2 over N)
//   warps 8-11 : producers — A: cp.async planes -> buf; B: LDG fp32 one
//                barrier-period ahead -> split2 -> buf.
// iter t: producers fill buf[t&1] with chunk t; consumers MMA buf[(t-1)&1];
// one __syncthreads per iter. Output fp32 partials -> g_part[z][m][n].
// ---------------------------------------------------------------------------
__global__ void __launch_bounds__(384, 1) sgemm_tc(const float* __restrict__ Bw,
                                                   int N, int klen) {
    extern __shared__ char smem[];
    uint32_t sb = smem_u32(smem);
    int tid = threadIdx.x, wid = tid >> 5, lid = tid & 31;
    int m0 = blockIdx.y * 128, n0 = blockIdx.x * 128, z = blockIdx.z;
    int nch = klen / 64;
    long k0 = (long)z * klen;
    const float4 z4 = make_float4(0.f, 0.f, 0.f, 0.f);

    if (wid >= 8) {
        // ================= producer warps (128 threads) =================
        int pid = tid - 256;                 // 0..127
        // A: one row per thread, 8 x 16B per plane per chunk
        int arow = m0 + pid;
        const uint16_t* Ah = g_Ah + (long)arow * KKT;
        const uint16_t* Al = g_Al + (long)arow * KKT;
        int asz = (arow < MM) ? 16 : 0;
        uint32_t adsth = sb + OFF_AH + swz((uint32_t)(pid * 128));
        // note: swz varies per 16B j-step; compute inside loop.
        // B: rows p*8+rbp (p=0..15), cols f4p*4..+3
        int rbp = pid >> 4, f4p = pid & 15;
        const float* Brow = Bw + (long)(n0 + rbp) * KKT + f4p * 4;
        bool bmask[16];
#pragma unroll
        for (int p = 0; p < 16; p++) bmask[p] = (n0 + p * 8 + rbp) < N;
        float4 b4[16];
#pragma unroll
        for (int p = 0; p < 16; p++)
            b4[p] = bmask[p] ? *(const float4*)(Brow + (long)p * 8 * KKT + k0) : z4;

        (void)adsth;
        for (int t = 0; t <= nch; t++) {
            if (t < nch) {
                uint32_t bufb = sb + (t & 1) * BUF_BYTES;
                char*    bbp  = smem + (t & 1) * BUF_BYTES;
                long kc = k0 + (long)t * 64;
                // (1) A planes via cp.async (issued first; waited at end)
#pragma unroll
                for (int j = 0; j < 8; j++) {
                    uint32_t sw = swz((uint32_t)(pid * 128 + j * 16));
                    cpa16(bufb + OFF_AH + sw, Ah + kc + j * 8, asz);
                    cpa16(bufb + OFF_AL + sw, Al + kc + j * 8, asz);
                }
                asm volatile("cp.async.commit_group;" ::: "memory");
                // (2) convert/store B chunk t from regs
#pragma unroll
                for (int p = 0; p < 16; p++) {
                    int r = p * 8 + rbp;
                    uint32_t sw = swz((uint32_t)(r * 128 + f4p * 8));
                    uint32_t h0, l0, h1, l1;
                    split2(b4[p].x, b4[p].y, h0, l0);
                    split2(b4[p].z, b4[p].w, h1, l1);
                    *(uint2*)(bbp + OFF_BH + sw) = make_uint2(h0, h1);
                    *(uint2*)(bbp + OFF_BL + sw) = make_uint2(l0, l1);
                }
                // (3) LDG B chunk t+1 (completes during consumers' next MMA)
                if (t + 1 < nch) {
                    long kc2 = k0 + (long)(t + 1) * 64;
#pragma unroll
                    for (int p = 0; p < 16; p++)
                        b4[p] = bmask[p] ? *(const float4*)(Brow + (long)p * 8 * KKT + kc2) : z4;
                }
                // (4) A cp.async must land before consumers read after sync
                asm volatile("cp.async.wait_group 0;" ::: "memory");
            }
            __syncthreads();
        }
        // producers exit after final sync (no epilogue work)
    } else {
        // ================= MMA consumer warps (R8 tiling) =================
        int wm = wid & 3, wn = wid >> 2;
        float acc[2][8][4];
#pragma unroll
        for (int i = 0; i < 2; i++)
#pragma unroll
            for (int j = 0; j < 8; j++)
#pragma unroll
                for (int q = 0; q < 4; q++) acc[i][j][q] = 0.f;

        for (int t = 0; t <= nch; t++) {
            if (t > 0) {
                uint32_t sbuf = sb + ((t - 1) & 1) * BUF_BYTES;
#pragma unroll
                for (int ks = 0; ks < 4; ks++) {
                    uint32_t ah[2][4], al[2][4];
#pragma unroll
                    for (int mf = 0; mf < 2; mf++) {
                        uint32_t row = (uint32_t)(wm * 32 + mf * 16 + (lid & 15));
                        uint32_t col = (uint32_t)(ks * 32 + (lid >> 4) * 16);
                        uint32_t o = swz(row * 128 + col);
                        ldsm4(ah[mf], sbuf + OFF_AH + o);
                        ldsm4(al[mf], sbuf + OFF_AL + o);
                    }
#pragma unroll
                    for (int nq = 0; nq < 4; nq++) {
                        uint32_t row = (uint32_t)(wn * 64 + nq * 16 + (lid & 7) +
                                                  ((lid >> 4) & 1) * 8);
                        uint32_t col = (uint32_t)(ks * 32 + ((lid >> 3) & 1) * 16);
                        uint32_t o = swz(row * 128 + col);
                        uint32_t bh[4], bl[4];
                        ldsm4(bh, sbuf + OFF_BH + o);
                        ldsm4(bl, sbuf + OFF_BL + o);
#pragma unroll
                        for (int mf = 0; mf < 2; mf++) {
                            mma16816(acc[mf][2 * nq + 0], ah[mf], bh + 0);
                            mma16816(acc[mf][2 * nq + 0], ah[mf], bl + 0);
                            mma16816(acc[mf][2 * nq + 0], al[mf], bh + 0);
                            mma16816(acc[mf][2 * nq + 1], ah[mf], bh + 2);
                            mma16816(acc[mf][2 * nq + 1], ah[mf], bl + 2);
                            mma16816(acc[mf][2 * nq + 1], al[mf], bh + 2);
                        }
                    }
                }
            }
            __syncthreads();
        }

        // epilogue: d-frag mapping: rows lane/4 (+8), cols (lane%4)*2 (+1)
        float* dst = g_part + (long)z * MM * N;
        int gr = lid >> 2, gc = (lid & 3) << 1;
#pragma unroll
        for (int mf = 0; mf < 2; mf++) {
#pragma unroll
            for (int nf = 0; nf < 8; nf++) {
                int mrow = m0 + wm * 32 + mf * 16 + gr;
                int ncol = n0 + wn * 64 + nf * 8 + gc;
                if (mrow < MM) {
                    if (ncol < N)     dst[(long)mrow * N + ncol]     = acc[mf][nf][0];
                    if (ncol + 1 < N) dst[(long)mrow * N + ncol + 1] = acc[mf][nf][1];
                }
                if (mrow + 8 < MM) {
                    if (ncol < N)     dst[(long)(mrow + 8) * N + ncol]     = acc[mf][nf][2];
                    if (ncol + 1 < N) dst[(long)(mrow + 8) * N + ncol + 1] = acc[mf][nf][3];
                }
            }
        }
    }
}

// ---------------------------------------------------------------------------
// im2col from x [8,2048,10,10], k=3 s=2 p=1 -> A planes [m][c*9+u*3+v]
// ---------------------------------------------------------------------------
__global__ void im2col_x_k(const float* __restrict__ x) {
    int t = blockIdx.x * 256 + threadIdx.x;
    if (t >= MM * CCH) return;
    int c = t & 2047, m = t >> 11;
    int b = m / 25, pos = m % 25;
    int oy = pos / 5, ox = pos % 5;
    const float* xb = x + ((long)(b * CCH + c)) * 100;
    long base = (long)m * KKT + c * 9;
#pragma unroll
    for (int u = 0; u < 3; u++) {
        int iy = 2 * oy - 1 + u;
#pragma unroll
        for (int v = 0; v < 3; v++) {
            int ix = 2 * ox - 1 + v;
            float val = (iy >= 0 && iy < 10 && ix >= 0 && ix < 10) ? xb[iy * 10 + ix] : 0.f;
            uint16_t h, l;
            split1(val, h, l);
            g_Ah[base + u * 3 + v] = h;
            g_Al[base + u * 3 + v] = l;
        }
    }
}

// im2col from a 5x5 map (layout [b][pos][c]), k=3 s=1 p=1. sel: 0->g_f, 1->g_xs
__global__ void im2col5_k(int sel) {
    int t = blockIdx.x * 256 + threadIdx.x;
    if (t >= MM * CCH) return;
    int c = t & 2047, m = t >> 11;
    int b = m / 25, pos = m % 25;
    int oy = pos / 5, ox = pos % 5;
    const float* src = sel ? g_xs : g_f;
    long base = (long)m * KKT + c * 9;
#pragma unroll
    for (int u = 0; u < 3; u++) {
        int iy = oy - 1 + u;
#pragma unroll
        for (int v = 0; v < 3; v++) {
            int ix = ox - 1 + v;
            float val = (iy >= 0 && iy < 5 && ix >= 0 && ix < 5)
                        ? src[(b * 25 + iy * 5 + ix) * CCH + c] : 0.f;
            uint16_t h, l;
            split1(val, h, l);
            g_Ah[base + u * 3 + v] = h;
            g_Al[base + u * 3 + v] = l;
        }
    }
}

// split-K reduction: dst_sel 0 -> g_C, 1 -> g_h, 2 -> g_L
__global__ void reduce_k(int dst_sel, int N, int nz) {
    int i = blockIdx.x * 256 + threadIdx.x;
    int tot = MM * N;
    if (i >= tot) return;
    float s = 0.f;
    for (int zz = 0; zz < nz; zz++) s += g_part[(long)zz * tot + i];
    float* dst = (dst_sel == 0) ? g_C : ((dst_sel == 1) ? g_h : g_L);
    dst[i] = s;
}

// BN batch statistics over m (200 samples) per channel n (of g_C)
__global__ void bn_stats_k() {
    __shared__ float ss[2], ss2[2];
    int n = blockIdx.x, tid = threadIdx.x;
    float s = 0.f, s2 = 0.f;
    for (int m = tid; m < MM; m += 64) {
        float v = g_C[(long)m * CCH + n];
        s += v; s2 += v * v;
    }
#pragma unroll
    for (int o = 16; o > 0; o >>= 1) {
        s  += __shfl_xor_sync(0xffffffffu, s,  o);
        s2 += __shfl_xor_sync(0xffffffffu, s2, o);
    }
    if ((tid & 31) == 0) { ss[tid >> 5] = s; ss2[tid >> 5] = s2; }
    __syncthreads();
    if (tid == 0) {
        float S = ss[0] + ss[1], S2 = ss2[0] + ss2[1];
        float mean = S * (1.f / 200.f);
        float var  = S2 * (1.f / 200.f) - mean * mean;
        g_mean[n] = mean;
        g_rstd[n] = rsqrtf(var + 1e-5f);
    }
}

// dst_sel: 0 -> g_f, 1 -> g_xs
__global__ void bn_apply_k(const float* __restrict__ gam, const float* __restrict__ bet,
                           int dst_sel, int relu) {
    int i = blockIdx.x * 256 + threadIdx.x;
    if (i >= MM * CCH) return;
    int n = i & 2047;
    float v = (g_C[i] - g_mean[n]) * g_rstd[n] * gam[n] + bet[n];
    if (relu) v = fmaxf(v, 0.f);
    float* dst = dst_sel ? g_xs : g_f;
    dst[i] = v;
}

// fc2 (4x512) per (b,pos) on relu(g_h); theta -> output; 9 grid pts -> g_grids
__global__ void fc2_theta_k(const float* __restrict__ fc2_w, float* __restrict__ out_theta) {
    int m = blockIdx.x;
    int tid = threadIdx.x;    // 128
    __shared__ float sh[512];
    __shared__ float sp[4];
    for (int i = tid; i < 512; i += 128) sh[i] = fmaxf(g_h[m * 512 + i], 0.f);
    __syncthreads();
    int w = tid >> 5, lane = tid & 31;
    float s = 0.f;
    for (int j = lane; j < 512; j += 32) s += sh[j] * fc2_w[w * 512 + j];
#pragma unroll
    for (int o = 16; o > 0; o >>= 1) s += __shfl_xor_sync(0xffffffffu, s, o);
    if (lane == 0) sp[w] = s;
    __syncthreads();
    if (tid == 0) {
        float p0 = sp[0], p1 = sp[1], p2 = sp[2], p3 = sp[3];
        float th[6] = {1.f + p0, 0.f, p1, 0.f, 1.f + p2, p3};
#pragma unroll
        for (int t = 0; t < 6; t++) out_theta[m * 6 + t] = th[t];
        int pi = (m % 25) / 5, pj = (m % 25) % 5;
#pragma unroll
        for (int u = 0; u < 3; u++)
#pragma unroll
            for (int v = 0; v < 3; v++) {
                float lx = (float)(pj + v) * (1.f / 3.f) - 1.f;
                float ly = (float)(pi + u) * (1.f / 3.f) - 1.f;
                int pt = m * 9 + u * 3 + v;
                g_grids[pt * 2 + 0] = (1.f + p0) * lx + p1;
                g_grids[pt * 2 + 1] = (1.f + p2) * ly + p3;
            }
    }
}

// bilinear sample of f (zero-padded ring), writes A planes [m][c*9+k]
__global__ void sample_k(void) {
    int pt = blockIdx.x;          // m*9 + k
    int m = pt / 9, k = pt % 9;
    int b = m / 25;
    float gx = (g_grids[pt * 2 + 0] + 1.f) * 3.f;
    float gy = (g_grids[pt * 2 + 1] + 1.f) * 3.f;
    float x0f = floorf(gx), y0f = floorf(gy);
    int   x0i = (int)x0f,  y0i = (int)y0f;
    float wx1 = gx - x0f, wx0 = 1.f - wx1;
    float wy1 = gy - y0f, wy0 = 1.f - wy1;
    int   cx[2] = {x0i, x0i + 1}, cy[2] = {y0i, y0i + 1};
    float wxx[2] = {wx0, wx1},    wyy[2] = {wy0, wy1};
    float wgt[4];
    int   off[4];
#pragma unroll
    for (int a = 0; a < 2; a++)
#pragma unroll
        for (int c2 = 0; c2 < 2; c2++) {
            int xi = cx[c2], yi = cy[a];
            bool val = (xi >= 1 && xi <= 5 && yi >= 1 && yi <= 5);
            wgt[a * 2 + c2] = val ? wyy[a] * wxx[c2] : 0.f;
            off[a * 2 + c2] = val ? ((b * 25 + (yi - 1) * 5 + (xi - 1)) * CCH) : 0;
        }
    long base = (long)m * KKT + k;
    for (int c = threadIdx.x; c < CCH; c += blockDim.x) {
        float v = wgt[0] * g_f[off[0] + c] + wgt[1] * g_f[off[1] + c]
                + wgt[2] * g_f[off[2] + c] + wgt[3] * g_f[off[3] + c];
        uint16_t h, l;
        split1(v, h, l);
        g_Ah[base + (long)c * 9] = h;
        g_Al[base + (long)c * 9] = l;
    }
}

// joint softmax over 201*25 per batch
__global__ void softmax_k(const float* __restrict__ bias, float* __restrict__ out) {
    int b = blockIdx.x;
    int tid = threadIdx.x;            // 512
    __shared__ float sm[5025];
    __shared__ float red[512];
    float lmax = -3.0e38f;
    for (int idx = tid; idx < 5025; idx += 512) {
        int o = idx / 25, pos = idx % 25;
        float v = g_L[(b * 25 + pos) * 201 + o] + bias[o];
        sm[idx] = v;
        lmax = fmaxf(lmax, v);
    }
    red[tid] = lmax;
    __syncthreads();
    for (int s = 256; s > 0; s >>= 1) {
        if (tid < s) red[tid] = fmaxf(red[tid], red[tid + s]);
        __syncthreads();
    }
    float mx = red[0];
    __syncthreads();
    float lsum = 0.f;
    for (int idx = tid; idx < 5025; idx += 512) {
        float e = expf(sm[idx] - mx);
        sm[idx] = e;
        lsum += e;
    }
    red[tid] = lsum;
    __syncthreads();
    for (int s = 256; s > 0; s >>= 1) {
        if (tid < s) red[tid] += red[tid + s];
        __syncthreads();
    }
    float inv = 1.f / red[0];
    __syncthreads();
    float* s_out = out + 1608;
    for (int idx = tid; idx < 5025; idx += 512)
        s_out[b * 5025 + idx] = sm[idx] * inv;
    for (int o = tid; o < 201; o += 512) {
        float acc = 0.f;
        for (int pos = 0; pos < 25; pos++) acc += sm[o * 25 + pos];
        out[b * 201 + o] = acc * inv;
    }
}

// ---------------------------------------------------------------------------
extern "C" void kernel_launch(void* const* d_in, const int* in_sizes, int n_in,
                              void* d_out, int out_size) {
    const float* x           = (const float*)d_in[0];
    const float* conv_last_w = (const float*)d_in[3];
    const float* bn_last_g   = (const float*)d_in[4];
    const float* bn_last_b   = (const float*)d_in[5];
    const float* loc_w1      = (const float*)d_in[6];
    const float* loc_g1      = (const float*)d_in[7];
    const float* loc_b1      = (const float*)d_in[8];
    const float* loc_w2      = (const float*)d_in[9];
    const float* loc_g2      = (const float*)d_in[10];
    const float* loc_b2      = (const float*)d_in[11];
    const float* fc1_w       = (const float*)d_in[12];
    const float* fc2_w       = (const float*)d_in[13];
    const float* conv_stn_w  = (const float*)d_in[14];
    const float* conv_stn_b  = (const float*)d_in[15];
    float* out = (float*)d_out;
    float* out_theta = out + 1608 + 40200;

    cudaFuncSetAttribute(sgemm_tc, cudaFuncAttributeMaxDynamicSharedMemorySize,
                         SMEM_TC_BYTES);

    const int ELT_BLOCKS = (MM * CCH + 255) / 256;   // 1600

    // ---- backbone tail: conv_last + BN -> f ----
    im2col_x_k<<<ELT_BLOCKS, 256>>>(x);
    sgemm_tc<<<dim3(16, 2, 9), 384, SMEM_TC_BYTES>>>(conv_last_w, 2048, 2048);
    reduce_k<<<(MM * 2048 + 255) / 256, 256>>>(0, 2048, 9);
    bn_stats_k<<<2048, 64>>>();
    bn_apply_k<<<ELT_BLOCKS, 256>>>(bn_last_g, bn_last_b, 0, 0);

    // ---- localization conv1 ----
    im2col5_k<<<ELT_BLOCKS, 256>>>(0);
    sgemm_tc<<<dim3(16, 2, 9), 384, SMEM_TC_BYTES>>>(loc_w1, 2048, 2048);
    reduce_k<<<(MM * 2048 + 255) / 256, 256>>>(0, 2048, 9);
    bn_stats_k<<<2048, 64>>>();
    bn_apply_k<<<ELT_BLOCKS, 256>>>(loc_g1, loc_b1, 1, 1);

    // ---- localization conv2 ----
    im2col5_k<<<ELT_BLOCKS, 256>>>(1);
    sgemm_tc<<<dim3(16, 2, 9), 384, SMEM_TC_BYTES>>>(loc_w2, 2048, 2048);
    reduce_k<<<(MM * 2048 + 255) / 256, 256>>>(0, 2048, 9);
    bn_stats_k<<<2048, 64>>>();
    bn_apply_k<<<ELT_BLOCKS, 256>>>(loc_g2, loc_b2, 1, 1);

    // ---- fc1 (3x3 conv, 512 outputs) ----
    im2col5_k<<<ELT_BLOCKS, 256>>>(1);
    sgemm_tc<<<dim3(4, 2, 18), 384, SMEM_TC_BYTES>>>(fc1_w, 512, 1024);
    reduce_k<<<(MM * 512 + 255) / 256, 256>>>(1, 512, 18);

    // ---- fc2 + theta + grids ----
    fc2_theta_k<<<200, 128>>>(fc2_w, out_theta);

    // ---- bilinear sample -> A planes ----
    sample_k<<<1800, 256>>>();

    // ---- conv_stn GEMM ----
    sgemm_tc<<<dim3(2, 2, 36), 384, SMEM_TC_BYTES>>>(conv_stn_w, 201, 512);
    reduce_k<<<(MM * 201 + 255) / 256, 256>>>(2, 201, 36);

    // ---- joint softmax + outputs ----
    softmax_k<<<8, 512>>>(conv_stn_b, out);
}

// round 16
// speedup vs baseline: 1.2440x; 1.0723x over previous
#include <cuda_runtime.h>
#include <cuda_bf16.h>
#include <cuda_fp16.h>
#include <cstdint>

// ---------------------------------------------------------------------------
// Net_15762529976343 — STN head. 5 GEMMs (M=200, K=18432). Harness PTX targets
// plain sm_103 (no tcgen05) -> mma.sync tensor cores.
// R16: MMA-issue-bound (R15 falsified overhead theories). Cut MMA count:
//   - three big N=2048 GEMMs: asymmetric fp16 2-term (A=fp16 hi+lo, B=fp16
//     single plane): 2 MMAs per k16 instead of 3 (-33% HMMA), B ldsm/convert
//     halved. Error ~2^-12/layer -> predicted out rel_err ~1-3e-4.
//   - fc1 + conv_stn keep the proven R8 bf16 3-term kernel (exact logits path).
// ---------------------------------------------------------------------------

#define MM   200
#define KKT  18432
#define CCH  2048

// ---- scratch ----
__device__ __align__(128) float g_A[MM * KKT];
__device__ __align__(128) float g_C[MM * CCH];
__device__ __align__(128) float g_f[MM * CCH];
__device__ __align__(128) float g_xs[MM * CCH];
__device__ __align__(128) float g_h[MM * 512];
__device__ __align__(128) float g_L[MM * 201];
__device__ __align__(128) float g_part[3686400];      // 9*200*2048 fp32 max
__device__ float g_mean[CCH], g_rstd[CCH];
__device__ float g_grids[8 * 225 * 2];

// ---------------------------------------------------------------------------
// helpers
// ---------------------------------------------------------------------------
__device__ __forceinline__ uint32_t smem_u32(const void* p) {
    uint32_t a;
    asm("{ .reg .u64 t; cvta.to.shared.u64 t, %1; cvt.u32.u64 %0, t; }"
        : "=r"(a) : "l"(p));
    return a;
}
__device__ __forceinline__ uint32_t swz(uint32_t off) {
    return off ^ ((off >> 3) & 0x70);
}
// fp32 pair -> packed bf16x2 (hi) and bf16x2 (lo)
__device__ __forceinline__ void split2(float x, float y, uint32_t& hi, uint32_t& lo) {
    __nv_bfloat16 hx = __float2bfloat16(x), hy = __float2bfloat16(y);
    float lx = x - __bfloat162float(hx), ly = y - __bfloat162float(hy);
    hi = ((uint32_t)__bfloat16_as_ushort(hy) << 16) | (uint32_t)__bfloat16_as_ushort(hx);
    __nv_bfloat16 gx = __float2bfloat16(lx), gy = __float2bfloat16(ly);
    lo = ((uint32_t)__bfloat16_as_ushort(gy) << 16) | (uint32_t)__bfloat16_as_ushort(gx);
}
// fp32 pair -> packed fp16x2 (hi) and fp16x2 (lo)
__device__ __forceinline__ void split2h(float x, float y, uint32_t& hi, uint32_t& lo) {
    __half hx = __float2half_rn(x), hy = __float2half_rn(y);
    float lx = x - __half2float(hx), ly = y - __half2float(hy);
    hi = ((uint32_t)__half_as_ushort(hy) << 16) | (uint32_t)__half_as_ushort(hx);
    __half gx = __float2half_rn(lx), gy = __float2half_rn(ly);
    lo = ((uint32_t)__half_as_ushort(gy) << 16) | (uint32_t)__half_as_ushort(gx);
}
// fp32 pair -> packed fp16x2 (round-to-nearest)
__device__ __forceinline__ uint32_t packh(float x, float y) {
    __half hx = __float2half_rn(x), hy = __float2half_rn(y);
    return ((uint32_t)__half_as_ushort(hy) << 16) | (uint32_t)__half_as_ushort(hx);
}
__device__ __forceinline__ void ldsm4(uint32_t* r, uint32_t addr) {
    asm volatile("ldmatrix.sync.aligned.m8n8.x4.shared.b16 {%0,%1,%2,%3}, [%4];"
                 : "=r"(r[0]), "=r"(r[1]), "=r"(r[2]), "=r"(r[3]) : "r"(addr));
}
__device__ __forceinline__ void mma16816(float* d, const uint32_t* a, const uint32_t* b) {
    asm volatile(
        "mma.sync.aligned.m16n8k16.row.col.f32.bf16.bf16.f32 "
        "{%0,%1,%2,%3},{%4,%5,%6,%7},{%8,%9},{%0,%1,%2,%3};"
        : "+f"(d[0]), "+f"(d[1]), "+f"(d[2]), "+f"(d[3])
        : "r"(a[0]), "r"(a[1]), "r"(a[2]), "r"(a[3]), "r"(b[0]), "r"(b[1]));
}
__device__ __forceinline__ void mma16816h(float* d, const uint32_t* a, const uint32_t* b) {
    asm volatile(
        "mma.sync.aligned.m16n8k16.row.col.f32.f16.f16.f32 "
        "{%0,%1,%2,%3},{%4,%5,%6,%7},{%8,%9},{%0,%1,%2,%3};"
        : "+f"(d[0]), "+f"(d[1]), "+f"(d[2]), "+f"(d[3])
        : "r"(a[0]), "r"(a[1]), "r"(a[2]), "r"(a[3]), "r"(b[0]), "r"(b[1]));
}

// bf16 3-term SMEM planes (single buffer, 64KB): [AH][AL][BH][BL]
#define OFF_AH 0
#define OFF_AL 16384
#define OFF_BH 32768
#define OFF_BL 49152
#define SMEM_TC_BYTES 65536
// fp16 2-term SMEM planes (single buffer, 48KB): [AH][AL][BH]
#define SMEM_F16_BYTES 49152

// ---------------------------------------------------------------------------
// bf16 3-term GEMM (R8-exact, proven 742us path). Used for fc1 + conv_stn.
// C[m,n] = sum_k A[m,k]*Bw[n,k]; A = g_A fp32; partials -> g_part[z].
// ---------------------------------------------------------------------------
__global__ void __launch_bounds__(256, 1) sgemm_tc(const float* __restrict__ Bw,
                                                   int N, int klen) {
    extern __shared__ char smem[];
    uint32_t sb = smem_u32(smem);
    int tid = threadIdx.x, wid = tid >> 5, lid = tid & 31;
    int m0 = blockIdx.y * 128, n0 = blockIdx.x * 128, z = blockIdx.z;
    int nch = klen / 64;
    long k0 = (long)z * klen;
    int f4 = tid & 15, rb = tid >> 4;
    const float4 z4 = make_float4(0.f, 0.f, 0.f, 0.f);

    int wm = wid & 3, wn = wid >> 2;
    float acc[2][8][4];
#pragma unroll
    for (int i = 0; i < 2; i++)
#pragma unroll
        for (int j = 0; j < 8; j++)
#pragma unroll
            for (int q = 0; q < 4; q++) acc[i][j][q] = 0.f;

    const float* Arow = g_A + (long)(m0 + rb) * KKT + f4 * 4;
    const float* Brow = Bw  + (long)(n0 + rb) * KKT + f4 * 4;
    bool amask[8], bmask[8];
#pragma unroll
    for (int p = 0; p < 8; p++) {
        amask[p] = (m0 + p * 16 + rb) < MM;
        bmask[p] = (n0 + p * 16 + rb) < N;
    }

    float4 a4[8], b4[8];
#pragma unroll
    for (int p = 0; p < 8; p++) {
        a4[p] = amask[p] ? *(const float4*)(Arow + (long)p * 16 * KKT + k0) : z4;
        b4[p] = bmask[p] ? *(const float4*)(Brow + (long)p * 16 * KKT + k0) : z4;
    }

    for (int ch = 0; ch < nch; ch++) {
#pragma unroll
        for (int p = 0; p < 8; p++) {
            int r = p * 16 + rb;
            uint32_t sw = swz((uint32_t)(r * 128 + f4 * 8));
            uint32_t h0, l0, h1, l1;
            split2(a4[p].x, a4[p].y, h0, l0); split2(a4[p].z, a4[p].w, h1, l1);
            *(uint2*)(smem + OFF_AH + sw) = make_uint2(h0, h1);
            *(uint2*)(smem + OFF_AL + sw) = make_uint2(l0, l1);
            split2(b4[p].x, b4[p].y, h0, l0); split2(b4[p].z, b4[p].w, h1, l1);
            *(uint2*)(smem + OFF_BH + sw) = make_uint2(h0, h1);
            *(uint2*)(smem + OFF_BL + sw) = make_uint2(l0, l1);
        }
        __syncthreads();

        if (ch + 1 < nch) {
            long kc = k0 + (long)(ch + 1) * 64;
#pragma unroll
            for (int p = 0; p < 8; p++) {
                a4[p] = amask[p] ? *(const float4*)(Arow + (long)p * 16 * KKT + kc) : z4;
                b4[p] = bmask[p] ? *(const float4*)(Brow + (long)p * 16 * KKT + kc) : z4;
            }
        }

#pragma unroll
        for (int ks = 0; ks < 4; ks++) {
            uint32_t ah[2][4], al[2][4];
#pragma unroll
            for (int mf = 0; mf < 2; mf++) {
                uint32_t row = (uint32_t)(wm * 32 + mf * 16 + (lid & 15));
                uint32_t col = (uint32_t)(ks * 32 + (lid >> 4) * 16);
                uint32_t o = swz(row * 128 + col);
                ldsm4(ah[mf], sb + OFF_AH + o);
                ldsm4(al[mf], sb + OFF_AL + o);
            }
#pragma unroll
            for (int nq = 0; nq < 4; nq++) {
                uint32_t row = (uint32_t)(wn * 64 + nq * 16 + (lid & 7) +
                                          ((lid >> 4) & 1) * 8);
                uint32_t col = (uint32_t)(ks * 32 + ((lid >> 3) & 1) * 16);
                uint32_t o = swz(row * 128 + col);
                uint32_t bh[4], bl[4];
                ldsm4(bh, sb + OFF_BH + o);
                ldsm4(bl, sb + OFF_BL + o);
#pragma unroll
                for (int mf = 0; mf < 2; mf++) {
                    mma16816(acc[mf][2 * nq + 0], ah[mf], bh + 0);
                    mma16816(acc[mf][2 * nq + 0], ah[mf], bl + 0);
                    mma16816(acc[mf][2 * nq + 0], al[mf], bh + 0);
                    mma16816(acc[mf][2 * nq + 1], ah[mf], bh + 2);
                    mma16816(acc[mf][2 * nq + 1], ah[mf], bl + 2);
                    mma16816(acc[mf][2 * nq + 1], al[mf], bh + 2);
                }
            }
        }
        __syncthreads();
    }

    float* dst = g_part + (long)z * MM * N;
    int gr = lid >> 2, gc = (lid & 3) << 1;
#pragma unroll
    for (int mf = 0; mf < 2; mf++) {
#pragma unroll
        for (int nf = 0; nf < 8; nf++) {
            int mrow = m0 + wm * 32 + mf * 16 + gr;
            int ncol = n0 + wn * 64 + nf * 8 + gc;
            if (mrow < MM) {
                if (ncol < N)     dst[(long)mrow * N + ncol]     = acc[mf][nf][0];
                if (ncol + 1 < N) dst[(long)mrow * N + ncol + 1] = acc[mf][nf][1];
            }
            if (mrow + 8 < MM) {
                if (ncol < N)     dst[(long)(mrow + 8) * N + ncol]     = acc[mf][nf][2];
                if (ncol + 1 < N) dst[(long)(mrow + 8) * N + ncol + 1] = acc[mf][nf][3];
            }
        }
    }
}

// ---------------------------------------------------------------------------
// fp16 2-term GEMM (asymmetric: A = fp16 hi+lo, B = single fp16 plane).
// A·B ~= Ahi·Bh + Alo·Bh  (error = A·(B-Bh) ~ 2^-12 rel). 128 MMAs/warp/chunk
// vs 192 in the bf16 3-term path. Used for the three N=2048 GEMMs.
// ---------------------------------------------------------------------------
__global__ void __launch_bounds__(256, 1) sgemm_f16(const float* __restrict__ Bw,
                                                    int N, int klen) {
    extern __shared__ char smem[];
    uint32_t sb = smem_u32(smem);
    int tid = threadIdx.x, wid = tid >> 5, lid = tid & 31;
    int m0 = blockIdx.y * 128, n0 = blockIdx.x * 128, z = blockIdx.z;
    int nch = klen / 64;
    long k0 = (long)z * klen;
    int f4 = tid & 15, rb = tid >> 4;
    const float4 z4 = make_float4(0.f, 0.f, 0.f, 0.f);

    int wm = wid & 3, wn = wid >> 2;
    float acc[2][8][4];
#pragma unroll
    for (int i = 0; i < 2; i++)
#pragma unroll
        for (int j = 0; j < 8; j++)
#pragma unroll
            for (int q = 0; q < 4; q++) acc[i][j][q] = 0.f;

    const float* Arow = g_A + (long)(m0 + rb) * KKT + f4 * 4;
    const float* Brow = Bw  + (long)(n0 + rb) * KKT + f4 * 4;
    bool amask[8], bmask[8];
#pragma unroll
    for (int p = 0; p < 8; p++) {
        amask[p] = (m0 + p * 16 + rb) < MM;
        bmask[p] = (n0 + p * 16 + rb) < N;
    }

    float4 a4[8], b4[8];
#pragma unroll
    for (int p = 0; p < 8; p++) {
        a4[p] = amask[p] ? *(const float4*)(Arow + (long)p * 16 * KKT + k0) : z4;
        b4[p] = bmask[p] ? *(const float4*)(Brow + (long)p * 16 * KKT + k0) : z4;
    }

    for (int ch = 0; ch < nch; ch++) {
        // store: A -> fp16 hi/lo planes; B -> single fp16 plane
#pragma unroll
        for (int p = 0; p < 8; p++) {
            int r = p * 16 + rb;
            uint32_t sw = swz((uint32_t)(r * 128 + f4 * 8));
            uint32_t h0, l0, h1, l1;
            split2h(a4[p].x, a4[p].y, h0, l0); split2h(a4[p].z, a4[p].w, h1, l1);
            *(uint2*)(smem + OFF_AH + sw) = make_uint2(h0, h1);
            *(uint2*)(smem + OFF_AL + sw) = make_uint2(l0, l1);
            uint32_t b0 = packh(b4[p].x, b4[p].y);
            uint32_t b1 = packh(b4[p].z, b4[p].w);
            *(uint2*)(smem + OFF_BH + sw) = make_uint2(b0, b1);
        }
        __syncthreads();

        if (ch + 1 < nch) {
            long kc = k0 + (long)(ch + 1) * 64;
#pragma unroll
            for (int p = 0; p < 8; p++) {
                a4[p] = amask[p] ? *(const float4*)(Arow + (long)p * 16 * KKT + kc) : z4;
                b4[p] = bmask[p] ? *(const float4*)(Brow + (long)p * 16 * KKT + kc) : z4;
            }
        }

#pragma unroll
        for (int ks = 0; ks < 4; ks++) {
            uint32_t ah[2][4], al[2][4];
#pragma unroll
            for (int mf = 0; mf < 2; mf++) {
                uint32_t row = (uint32_t)(wm * 32 + mf * 16 + (lid & 15));
                uint32_t col = (uint32_t)(ks * 32 + (lid >> 4) * 16);
                uint32_t o = swz(row * 128 + col);
                ldsm4(ah[mf], sb + OFF_AH + o);
                ldsm4(al[mf], sb + OFF_AL + o);
            }
#pragma unroll
            for (int nq = 0; nq < 4; nq++) {
                uint32_t row = (uint32_t)(wn * 64 + nq * 16 + (lid & 7) +
                                          ((lid >> 4) & 1) * 8);
                uint32_t col = (uint32_t)(ks * 32 + ((lid >> 3) & 1) * 16);
                uint32_t o = swz(row * 128 + col);
                uint32_t bh[4];
                ldsm4(bh, sb + OFF_BH + o);
#pragma unroll
                for (int mf = 0; mf < 2; mf++) {
                    mma16816h(acc[mf][2 * nq + 0], ah[mf], bh + 0);
                    mma16816h(acc[mf][2 * nq + 0], al[mf], bh + 0);
                    mma16816h(acc[mf][2 * nq + 1], ah[mf], bh + 2);
                    mma16816h(acc[mf][2 * nq + 1], al[mf], bh + 2);
                }
            }
        }
        __syncthreads();
    }

    float* dst = g_part + (long)z * MM * N;
    int gr = lid >> 2, gc = (lid & 3) << 1;
#pragma unroll
    for (int mf = 0; mf < 2; mf++) {
#pragma unroll
        for (int nf = 0; nf < 8; nf++) {
            int mrow = m0 + wm * 32 + mf * 16 + gr;
            int ncol = n0 + wn * 64 + nf * 8 + gc;
            if (mrow < MM) {
                if (ncol < N)     dst[(long)mrow * N + ncol]     = acc[mf][nf][0];
                if (ncol + 1 < N) dst[(long)mrow * N + ncol + 1] = acc[mf][nf][1];
            }
            if (mrow + 8 < MM) {
                if (ncol < N)     dst[(long)(mrow + 8) * N + ncol]     = acc[mf][nf][2];
                if (ncol + 1 < N) dst[(long)(mrow + 8) * N + ncol + 1] = acc[mf][nf][3];
            }
        }
    }
}

// ---------------------------------------------------------------------------
// im2col from x [8,2048,10,10], k=3 s=2 p=1  -> A[m][c*9+u*3+v]
// ---------------------------------------------------------------------------
__global__ void im2col_x_k(const float* __restrict__ x) {
    int t = blockIdx.x * 256 + threadIdx.x;
    if (t >= MM * CCH) return;
    int c = t & 2047, m = t >> 11;
    int b = m / 25, pos = m % 25;
    int oy = pos / 5, ox = pos % 5;
    const float* xb = x + ((long)(b * CCH + c)) * 100;
    float* ab = g_A + (long)m * KKT + c * 9;
#pragma unroll
    for (int u = 0; u < 3; u++) {
        int iy = 2 * oy - 1 + u;
#pragma unroll
        for (int v = 0; v < 3; v++) {
            int ix = 2 * ox - 1 + v;
            float val = (iy >= 0 && iy < 10 && ix >= 0 && ix < 10) ? xb[iy * 10 + ix] : 0.f;
            ab[u * 3 + v] = val;
        }
    }
}

// im2col from a 5x5 map (layout [b][pos][c]), k=3 s=1 p=1. sel: 0->g_f, 1->g_xs
__global__ void im2col5_k(int sel) {
    int t = blockIdx.x * 256 + threadIdx.x;
    if (t >= MM * CCH) return;
    int c = t & 2047, m = t >> 11;
    int b = m / 25, pos = m % 25;
    int oy = pos / 5, ox = pos % 5;
    const float* src = sel ? g_xs : g_f;
    float* ab = g_A + (long)m * KKT + c * 9;
#pragma unroll
    for (int u = 0; u < 3; u++) {
        int iy = oy - 1 + u;
#pragma unroll
        for (int v = 0; v < 3; v++) {
            int ix = ox - 1 + v;
            float val = (iy >= 0 && iy < 5 && ix >= 0 && ix < 5)
                        ? src[(b * 25 + iy * 5 + ix) * CCH + c] : 0.f;
            ab[u * 3 + v] = val;
        }
    }
}

// split-K reduction: dst_sel 0 -> g_C, 1 -> g_h, 2 -> g_L
__global__ void reduce_k(int dst_sel, int N, int nz) {
    int i = blockIdx.x * 256 + threadIdx.x;
    int tot = MM * N;
    if (i >= tot) return;
    float s = 0.f;
    for (int zz = 0; zz < nz; zz++) s += g_part[(long)zz * tot + i];
    float* dst = (dst_sel == 0) ? g_C : ((dst_sel == 1) ? g_h : g_L);
    dst[i] = s;
}

// BN batch statistics over m (200 samples) per channel n (of g_C)
__global__ void bn_stats_k() {
    __shared__ float ss[2], ss2[2];
    int n = blockIdx.x, tid = threadIdx.x;
    float s = 0.f, s2 = 0.f;
    for (int m = tid; m < MM; m += 64) {
        float v = g_C[(long)m * CCH + n];
        s += v; s2 += v * v;
    }
#pragma unroll
    for (int o = 16; o > 0; o >>= 1) {
        s  += __shfl_xor_sync(0xffffffffu, s,  o);
        s2 += __shfl_xor_sync(0xffffffffu, s2, o);
    }
    if ((tid & 31) == 0) { ss[tid >> 5] = s; ss2[tid >> 5] = s2; }
    __syncthreads();
    if (tid == 0) {
        float S = ss[0] + ss[1], S2 = ss2[0] + ss2[1];
        float mean = S * (1.f / 200.f);
        float var  = S2 * (1.f / 200.f) - mean * mean;
        g_mean[n] = mean;
        g_rstd[n] = rsqrtf(var + 1e-5f);
    }
}

// dst_sel: 0 -> g_f, 1 -> g_xs
__global__ void bn_apply_k(const float* __restrict__ gam, const float* __restrict__ bet,
                           int dst_sel, int relu) {
    int i = blockIdx.x * 256 + threadIdx.x;
    if (i >= MM * CCH) return;
    int n = i & 2047;
    float v = (g_C[i] - g_mean[n]) * g_rstd[n] * gam[n] + bet[n];
    if (relu) v = fmaxf(v, 0.f);
    float* dst = dst_sel ? g_xs : g_f;
    dst[i] = v;
}

// fc2 (4x512) per (b,pos) on relu(g_h); theta -> output; 9 grid pts -> g_grids
__global__ void fc2_theta_k(const float* __restrict__ fc2_w, float* __restrict__ out_theta) {
    int m = blockIdx.x;
    int tid = threadIdx.x;    // 128
    __shared__ float sh[512];
    __shared__ float sp[4];
    for (int i = tid; i < 512; i += 128) sh[i] = fmaxf(g_h[m * 512 + i], 0.f);
    __syncthreads();
    int w = tid >> 5, lane = tid & 31;
    float s = 0.f;
    for (int j = lane; j < 512; j += 32) s += sh[j] * fc2_w[w * 512 + j];
#pragma unroll
    for (int o = 16; o > 0; o >>= 1) s += __shfl_xor_sync(0xffffffffu, s, o);
    if (lane == 0) sp[w] = s;
    __syncthreads();
    if (tid == 0) {
        float p0 = sp[0], p1 = sp[1], p2 = sp[2], p3 = sp[3];
        float th[6] = {1.f + p0, 0.f, p1, 0.f, 1.f + p2, p3};
#pragma unroll
        for (int t = 0; t < 6; t++) out_theta[m * 6 + t] = th[t];
        int pi = (m % 25) / 5, pj = (m % 25) % 5;
#pragma unroll
        for (int u = 0; u < 3; u++)
#pragma unroll
            for (int v = 0; v < 3; v++) {
                float lx = (float)(pj + v) * (1.f / 3.f) - 1.f;
                float ly = (float)(pi + u) * (1.f / 3.f) - 1.f;
                int pt = m * 9 + u * 3 + v;
                g_grids[pt * 2 + 0] = (1.f + p0) * lx + p1;
                g_grids[pt * 2 + 1] = (1.f + p2) * ly + p3;
            }
    }
}

// bilinear sample of f (zero-padded ring), writes im2col A[m][c*9+k]
__global__ void sample_k(void) {
    int pt = blockIdx.x;          // m*9 + k
    int m = pt / 9, k = pt % 9;
    int b = m / 25;
    float gx = (g_grids[pt * 2 + 0] + 1.f) * 3.f;
    float gy = (g_grids[pt * 2 + 1] + 1.f) * 3.f;
    float x0f = floorf(gx), y0f = floorf(gy);
    int   x0i = (int)x0f,  y0i = (int)y0f;
    float wx1 = gx - x0f, wx0 = 1.f - wx1;
    float wy1 = gy - y0f, wy0 = 1.f - wy1;
    int   cx[2] = {x0i, x0i + 1}, cy[2] = {y0i, y0i + 1};
    float wxx[2] = {wx0, wx1},    wyy[2] = {wy0, wy1};
    float wgt[4];
    int   off[4];
#pragma unroll
    for (int a = 0; a < 2; a++)
#pragma unroll
        for (int c2 = 0; c2 < 2; c2++) {
            int xi = cx[c2], yi = cy[a];
            bool val = (xi >= 1 && xi <= 5 && yi >= 1 && yi <= 5);
            wgt[a * 2 + c2] = val ? wyy[a] * wxx[c2] : 0.f;
            off[a * 2 + c2] = val ? ((b * 25 + (yi - 1) * 5 + (xi - 1)) * CCH) : 0;
        }
    float* ab = g_A + (long)m * KKT + k;
    for (int c = threadIdx.x; c < CCH; c += blockDim.x) {
        float v = wgt[0] * g_f[off[0] + c] + wgt[1] * g_f[off[1] + c]
                + wgt[2] * g_f[off[2] + c] + wgt[3] * g_f[off[3] + c];
        ab[(long)c * 9] = v;
    }
}

// joint softmax over 201*25 per batch
__global__ void softmax_k(const float* __restrict__ bias, float* __restrict__ out) {
    int b = blockIdx.x;
    int tid = threadIdx.x;            // 512
    __shared__ float sm[5025];
    __shared__ float red[512];
    float lmax = -3.0e38f;
    for (int idx = tid; idx < 5025; idx += 512) {
        int o = idx / 25, pos = idx % 25;
        float v = g_L[(b * 25 + pos) * 201 + o] + bias[o];
        sm[idx] = v;
        lmax = fmaxf(lmax, v);
    }
    red[tid] = lmax;
    __syncthreads();
    for (int s = 256; s > 0; s >>= 1) {
        if (tid < s) red[tid] = fmaxf(red[tid], red[tid + s]);
        __syncthreads();
    }
    float mx = red[0];
    __syncthreads();
    float lsum = 0.f;
    for (int idx = tid; idx < 5025; idx += 512) {
        float e = expf(sm[idx] - mx);
        sm[idx] = e;
        lsum += e;
    }
    red[tid] = lsum;
    __syncthreads();
    for (int s = 256; s > 0; s >>= 1) {
        if (tid < s) red[tid] += red[tid + s];
        __syncthreads();
    }
    float inv = 1.f / red[0];
    __syncthreads();
    float* s_out = out + 1608;
    for (int idx = tid; idx < 5025; idx += 512)
        s_out[b * 5025 + idx] = sm[idx] * inv;
    for (int o = tid; o < 201; o += 512) {
        float acc = 0.f;
        for (int pos = 0; pos < 25; pos++) acc += sm[o * 25 + pos];
        out[b * 201 + o] = acc * inv;
    }
}

// ---------------------------------------------------------------------------
extern "C" void kernel_launch(void* const* d_in, const int* in_sizes, int n_in,
                              void* d_out, int out_size) {
    const float* x           = (const float*)d_in[0];
    const float* conv_last_w = (const float*)d_in[3];
    const float* bn_last_g   = (const float*)d_in[4];
    const float* bn_last_b   = (const float*)d_in[5];
    const float* loc_w1      = (const float*)d_in[6];
    const float* loc_g1      = (const float*)d_in[7];
    const float* loc_b1      = (const float*)d_in[8];
    const float* loc_w2      = (const float*)d_in[9];
    const float* loc_g2      = (const float*)d_in[10];
    const float* loc_b2      = (const float*)d_in[11];
    const float* fc1_w       = (const float*)d_in[12];
    const float* fc2_w       = (const float*)d_in[13];
    const float* conv_stn_w  = (const float*)d_in[14];
    const float* conv_stn_b  = (const float*)d_in[15];
    float* out = (float*)d_out;
    float* out_theta = out + 1608 + 40200;

    cudaFuncSetAttribute(sgemm_tc, cudaFuncAttributeMaxDynamicSharedMemorySize,
                         SMEM_TC_BYTES);
    cudaFuncSetAttribute(sgemm_f16, cudaFuncAttributeMaxDynamicSharedMemorySize,
                         SMEM_F16_BYTES);

    const int ELT_BLOCKS = (MM * CCH + 255) / 256;   // 1600

    // ---- backbone tail: conv_last + BN -> f ----
    im2col_x_k<<<ELT_BLOCKS, 256>>>(x);
    sgemm_f16<<<dim3(16, 2, 9), 256, SMEM_F16_BYTES>>>(conv_last_w, 2048, 2048);
    reduce_k<<<(MM * 2048 + 255) / 256, 256>>>(0, 2048, 9);
    bn_stats_k<<<2048, 64>>>();
    bn_apply_k<<<ELT_BLOCKS, 256>>>(bn_last_g, bn_last_b, 0, 0);

    // ---- localization conv1 ----
    im2col5_k<<<ELT_BLOCKS, 256>>>(0);
    sgemm_f16<<<dim3(16, 2, 9), 256, SMEM_F16_BYTES>>>(loc_w1, 2048, 2048);
    reduce_k<<<(MM * 2048 + 255) / 256, 256>>>(0, 2048, 9);
    bn_stats_k<<<2048, 64>>>();
    bn_apply_k<<<ELT_BLOCKS, 256>>>(loc_g1, loc_b1, 1, 1);

    // ---- localization conv2 ----
    im2col5_k<<<ELT_BLOCKS, 256>>>(1);
    sgemm_f16<<<dim3(16, 2, 9), 256, SMEM_F16_BYTES>>>(loc_w2, 2048, 2048);
    reduce_k<<<(MM * 2048 + 255) / 256, 256>>>(0, 2048, 9);
    bn_stats_k<<<2048, 64>>>();
    bn_apply_k<<<ELT_BLOCKS, 256>>>(loc_g2, loc_b2, 1, 1);

    // ---- fc1 (3x3 conv, 512 outputs) — bf16 3-term (exact path) ----
    im2col5_k<<<ELT_BLOCKS, 256>>>(1);
    sgemm_tc<<<dim3(4, 2, 18), 256, SMEM_TC_BYTES>>>(fc1_w, 512, 1024);
    reduce_k<<<(MM * 512 + 255) / 256, 256>>>(1, 512, 18);

    // ---- fc2 + theta + grids ----
    fc2_theta_k<<<200, 128>>>(fc2_w, out_theta);

    // ---- bilinear sample -> im2col A ----
    sample_k<<<1800, 256>>>();

    // ---- conv_stn GEMM — bf16 3-term (logits path) ----
    sgemm_tc<<<dim3(2, 2, 36), 256, SMEM_TC_BYTES>>>(conv_stn_w, 201, 512);
    reduce_k<<<(MM * 201 + 255) / 256, 256>>>(2, 201, 36);

    // ---- joint softmax + outputs ----
    softmax_k<<<8, 512>>>(conv_stn_b, out);
}